// round 8
// baseline (speedup 1.0000x reference)
#include <cuda_runtime.h>

#define N_ROWS (64 * 1024)
#define T_LEN  1200
#define WPB    8                        // warps per block
#define NBLOCKS (N_ROWS / WPB)          // 8192
#define BLOCKS_PER_BATCH 128            // 1024 nodes / 8 rows-per-block

// Scratch (allowed: __device__ globals, no allocation)
__device__ float        g_feat[N_ROWS];
// Per-batch completion counters, 256B apart (distinct LTS slices).
__device__ unsigned int g_cnt[64 * 64];

// ---------------------------------------------------------------------------
// Fused kernel: per-row temporal pipeline (one warp per row). Row data is
// first staged GMEM->SMEM with fully-coalesced float4 loads (4 lines/instr,
// the L1 wavefront minimum), then the conv/pool ladder runs out of SMEM.
// The LAST block of each batch (128 blocks/batch) computes that batch's
// classifier logits + softmax (64 independent elections).
// Lengths: 1200 -> 600 -> 200 -> 100 -> 50 -> 25 -> 12 -> 6 -> 3 -> 1
// ---------------------------------------------------------------------------
__global__ __launch_bounds__(WPB * 32)
void fused_kernel(
    const float* __restrict__ x,
    const float* __restrict__ c0_w, const float* __restrict__ c0_b,
    const float* __restrict__ c2_w, const float* __restrict__ c2_b,
    const float* __restrict__ c4_w, const float* __restrict__ c4_b,
    const float* __restrict__ c6_w, const float* __restrict__ c6_b,
    const float* __restrict__ c8_w, const float* __restrict__ c8_b,
    const float* __restrict__ cls_w, const float* __restrict__ cls_b,
    float* __restrict__ out)
{
    __shared__ float xs[WPB][1200];     // staged row (38.4 KB)
    __shared__ float sA[WPB][200];
    __shared__ float sB[WPB][100];
    __shared__ float s_red[3][WPB];
    __shared__ bool  s_last;

    const int warp = threadIdx.x >> 5;
    const int lane = threadIdx.x & 31;
    const int row  = blockIdx.x * WPB + warp;   // grid exactly covers N_ROWS

    const float* __restrict__ xr = x + (size_t)row * T_LEN;

    // --- Stage GMEM -> SMEM: 1200 floats = 300 float4, coalesced -----------
    {
        const float4* __restrict__ xg4 = reinterpret_cast<const float4*>(xr);
        float4* xs4 = reinterpret_cast<float4*>(xs[warp]);
        #pragma unroll
        for (int it = 0; it < 9; ++it)          // 9*32 = 288 unpredicated
            xs4[lane + 32 * it] = xg4[lane + 32 * it];
        if (lane < 12)                          // remaining 288..299
            xs4[288 + lane] = xg4[288 + lane];
    }
    __syncwarp();

    // --- Stage 0+1: conv(k=2,s=2) + maxpool3 + relu : 1200 -> 200 ----------
    const float w00 = c0_w[0], w01 = c0_w[1], b0 = c0_b[0];
    const float* xb = xs[warp];
    float* h2 = sA[warp];
    #pragma unroll
    for (int it = 0; it < 7; ++it) {
        int j = lane + 32 * it;            // 7*32 = 224 >= 200
        if (j < 200) {
            const float2* p = reinterpret_cast<const float2*>(xb + 6 * j);
            float2 a = p[0], b = p[1], c = p[2];
            float m0 = w00 * a.x + w01 * a.y;
            float m1 = w00 * b.x + w01 * b.y;
            float m2 = w00 * c.x + w01 * c.y;
            float m  = fmaxf(m0, fmaxf(m1, m2));
            h2[j] = fmaxf(m + b0, 0.0f);
        }
    }
    __syncwarp();

    // --- Stage 2: conv(k=4,s=2,p=1) : 200 -> 100 ---------------------------
    const float w20 = c2_w[0], w21 = c2_w[1], w22 = c2_w[2], w23 = c2_w[3], b2 = c2_b[0];
    float* y3 = sB[warp];
    #pragma unroll
    for (int it = 0; it < 4; ++it) {
        int i = lane + 32 * it;
        if (i < 100) {
            float v0 = (i == 0)          ? 0.0f : h2[2 * i - 1];
            float v1 = h2[2 * i];
            float v2 = h2[2 * i + 1];
            float v3 = (2 * i + 2 < 200) ? h2[2 * i + 2] : 0.0f;
            y3[i] = b2 + w20 * v0 + w21 * v1 + w22 * v2 + w23 * v3;
        }
    }
    __syncwarp();

    // --- Stage 3: maxpool2 + relu : 100 -> 50 -------------------------------
    float* h4 = sA[warp];
    #pragma unroll
    for (int it = 0; it < 2; ++it) {
        int i = lane + 32 * it;
        if (i < 50)
            h4[i] = fmaxf(fmaxf(y3[2 * i], y3[2 * i + 1]), 0.0f);
    }
    __syncwarp();

    // --- Stage 4: conv(k=4,s=2,p=1) : 50 -> 25 ------------------------------
    const float w40 = c4_w[0], w41 = c4_w[1], w42 = c4_w[2], w43 = c4_w[3], b4 = c4_b[0];
    float* y5 = sB[warp];
    if (lane < 25) {
        int i = lane;
        float v0 = (i == 0)         ? 0.0f : h4[2 * i - 1];
        float v1 = h4[2 * i];
        float v2 = h4[2 * i + 1];
        float v3 = (2 * i + 2 < 50) ? h4[2 * i + 2] : 0.0f;
        y5[i] = b4 + w40 * v0 + w41 * v1 + w42 * v2 + w43 * v3;
    }
    __syncwarp();

    // --- Stage 5: maxpool2 + relu : 25 -> 12 --------------------------------
    float* h6 = sA[warp];
    if (lane < 12)
        h6[lane] = fmaxf(fmaxf(y5[2 * lane], y5[2 * lane + 1]), 0.0f);
    __syncwarp();

    // --- Stage 6: conv(k=4,s=2,p=1) : 12 -> 6 -------------------------------
    const float w60 = c6_w[0], w61 = c6_w[1], w62 = c6_w[2], w63 = c6_w[3], b6 = c6_b[0];
    float* y7 = sB[warp];
    if (lane < 6) {
        int i = lane;
        float v0 = (i == 0)         ? 0.0f : h6[2 * i - 1];
        float v1 = h6[2 * i];
        float v2 = h6[2 * i + 1];
        float v3 = (2 * i + 2 < 12) ? h6[2 * i + 2] : 0.0f;
        y7[i] = b6 + w60 * v0 + w61 * v1 + w62 * v2 + w63 * v3;
    }
    __syncwarp();

    // --- Stage 7: maxpool2 + relu : 6 -> 3 ----------------------------------
    float* h8 = sA[warp];
    if (lane < 3)
        h8[lane] = fmaxf(fmaxf(y7[2 * lane], y7[2 * lane + 1]), 0.0f);
    __syncwarp();

    // --- Stage 8: conv(k=3,s=1,p=0) : 3 -> 1 --------------------------------
    if (lane == 0)
        g_feat[row] = c8_b[0] + c8_w[0] * h8[0] + c8_w[1] * h8[1] + c8_w[2] * h8[2];

    // ========================================================================
    // Per-batch last-block election (proven in R6: no atomic serialization).
    // ========================================================================
    const int b = blockIdx.x >> 7;               // batch id (128 blocks each)
    __syncthreads();                             // order all warps' g_feat STG
    if (threadIdx.x == 0) {
        __threadfence();                         // release this block's stores
        unsigned int prev = atomicAdd(&g_cnt[b * 64], 1u);
        s_last = (prev == (unsigned int)(BLOCKS_PER_BATCH - 1));
    }
    __syncthreads();
    if (!s_last) return;

    __threadfence();     // acquire: sibling blocks' g_feat stores visible

    // --- Classifier for batch b: logits[c] = feat[b,:].cls_w[c,:] + cls_b[c]
    {
        const float* __restrict__ f = g_feat + b * 1024;
        float a0 = 0.f, a1 = 0.f, a2 = 0.f;
        #pragma unroll
        for (int k = 0; k < 4; ++k) {
            int n = k * 256 + threadIdx.x;
            float v = __ldcg(f + n);
            a0 += v * __ldg(cls_w + n);
            a1 += v * __ldg(cls_w + 1024 + n);
            a2 += v * __ldg(cls_w + 2048 + n);
        }
        #pragma unroll
        for (int off = 16; off > 0; off >>= 1) {
            a0 += __shfl_down_sync(0xffffffffu, a0, off);
            a1 += __shfl_down_sync(0xffffffffu, a1, off);
            a2 += __shfl_down_sync(0xffffffffu, a2, off);
        }
        if (lane == 0) {
            s_red[0][warp] = a0;
            s_red[1][warp] = a1;
            s_red[2][warp] = a2;
        }
        __syncthreads();
        if (threadIdx.x == 0) {
            float l0 = cls_b[0], l1 = cls_b[1], l2 = cls_b[2];
            #pragma unroll
            for (int w = 0; w < WPB; ++w) {
                l0 += s_red[0][w];
                l1 += s_red[1][w];
                l2 += s_red[2][w];
            }
            float m  = fmaxf(l0, fmaxf(l1, l2));
            float e0 = expf(l0 - m), e1 = expf(l1 - m), e2 = expf(l2 - m);
            float inv = 1.0f / (e0 + e1 + e2);
            out[b * 3 + 0] = e0 * inv;
            out[b * 3 + 1] = e1 * inv;
            out[b * 3 + 2] = e2 * inv;
            g_cnt[b * 64] = 0;   // reset own counter for next graph replay
        }
    }
}

// ---------------------------------------------------------------------------
// Input order per metadata:
// 0:x 1:c0_w 2:c0_b 3:c2_w 4:c2_b 5:c4_w 6:c4_b 7:c6_w 8:c6_b 9:c8_w 10:c8_b
// 11..14: gcn weights (dead code, unused) 15:cls_w 16:cls_b
// ---------------------------------------------------------------------------
extern "C" void kernel_launch(void* const* d_in, const int* in_sizes, int n_in,
                              void* d_out, int out_size)
{
    const float* x     = (const float*)d_in[0];
    const float* c0_w  = (const float*)d_in[1];
    const float* c0_b  = (const float*)d_in[2];
    const float* c2_w  = (const float*)d_in[3];
    const float* c2_b  = (const float*)d_in[4];
    const float* c4_w  = (const float*)d_in[5];
    const float* c4_b  = (const float*)d_in[6];
    const float* c6_w  = (const float*)d_in[7];
    const float* c6_b  = (const float*)d_in[8];
    const float* c8_w  = (const float*)d_in[9];
    const float* c8_b  = (const float*)d_in[10];
    const float* cls_w = (const float*)d_in[15];
    const float* cls_b = (const float*)d_in[16];
    float* out = (float*)d_out;

    fused_kernel<<<NBLOCKS, WPB * 32>>>(
        x, c0_w, c0_b, c2_w, c2_b, c4_w, c4_b, c6_w, c6_b, c8_w, c8_b,
        cls_w, cls_b, out);
}

// round 10
// speedup vs baseline: 1.0325x; 1.0325x over previous
#include <cuda_runtime.h>

#define N_ROWS (64 * 1024)
#define T_LEN  1200
#define WPB    8                        // warps per block
#define NBLOCKS (N_ROWS / WPB)          // 8192
#define BLOCKS_PER_BATCH 128            // 1024 nodes / 8 rows-per-block
#define BUF    800                      // per-warp smem floats (mult of 32)

// Scratch (allowed: __device__ globals, no allocation)
__device__ float        g_feat[N_ROWS];
// Per-batch completion counters, 256B apart (distinct LTS slices).
__device__ unsigned int g_cnt[64 * 64];

// ---------------------------------------------------------------------------
// Fused kernel: one warp per row. Stage 0 conv(k=2,s=2) is computed DURING
// the coalesced float4 global load (each 16B chunk -> exactly 2 conv outputs,
// no overlap), so only the 600 conv outputs hit smem, not the 1200 raw floats.
// Ladder offsets within the 800-float per-warp buffer (all disjoint per stage):
//   c   [0..599]   conv0 outputs            (600)
//   h2  [600..799] pool3+relu               (200)
//   y3  [0..99]    conv2                    (100)   (c dead)
//   h4  [256..305] pool2+relu               (50)
//   y5  [0..24]    conv4                    (25)
//   h6  [128..139] pool2+relu               (12)
//   y7  [0..5]     conv6                    (6)
//   h8  [64..66]   pool2+relu               (3)
// Last block of each batch (128 blocks/batch) runs classifier + softmax.
// ---------------------------------------------------------------------------
__global__ __launch_bounds__(WPB * 32)
void fused_kernel(
    const float* __restrict__ x,
    const float* __restrict__ c0_w, const float* __restrict__ c0_b,
    const float* __restrict__ c2_w, const float* __restrict__ c2_b,
    const float* __restrict__ c4_w, const float* __restrict__ c4_b,
    const float* __restrict__ c6_w, const float* __restrict__ c6_b,
    const float* __restrict__ c8_w, const float* __restrict__ c8_b,
    const float* __restrict__ cls_w, const float* __restrict__ cls_b,
    float* __restrict__ out)
{
    __shared__ float sW[WPB][BUF];      // 25.6 KB
    __shared__ float s_red[3][WPB];
    __shared__ bool  s_last;

    const int warp = threadIdx.x >> 5;
    const int lane = threadIdx.x & 31;
    const int row  = blockIdx.x * WPB + warp;   // grid exactly covers N_ROWS

    float* buf = sW[warp];

    // --- Stage 0: conv(k=2,s=2) fused into coalesced float4 load -----------
    // 1200 -> 600. Lane loads x4[idx] (consecutive lanes, consecutive 16B),
    // emits conv outputs {2idx, 2idx+1} as one float2 store.
    {
        const float4* __restrict__ xg4 =
            reinterpret_cast<const float4*>(x + (size_t)row * T_LEN);
        const float w0 = c0_w[0], w1 = c0_w[1];
        float2* c2v = reinterpret_cast<float2*>(buf);
        #pragma unroll
        for (int it = 0; it < 9; ++it) {        // 9*32 = 288 unpredicated
            int idx = lane + 32 * it;
            float4 v = xg4[idx];
            c2v[idx] = make_float2(w0 * v.x + w1 * v.y, w0 * v.z + w1 * v.w);
        }
        if (lane < 12) {                        // remaining 288..299
            int idx = 288 + lane;
            float4 v = xg4[idx];
            c2v[idx] = make_float2(w0 * v.x + w1 * v.y, w0 * v.z + w1 * v.w);
        }
    }
    __syncwarp();

    // --- Stage 1: maxpool3 + relu : 600 -> 200 (stride-3 LDS, conflict-free)
    const float b0 = c0_b[0];
    float* h2 = buf + 600;
    #pragma unroll
    for (int it = 0; it < 7; ++it) {
        int j = lane + 32 * it;            // 7*32 = 224 >= 200
        if (j < 200) {
            float m = fmaxf(buf[3 * j], fmaxf(buf[3 * j + 1], buf[3 * j + 2]));
            h2[j] = fmaxf(m + b0, 0.0f);
        }
    }
    __syncwarp();

    // --- Stage 2: conv(k=4,s=2,p=1) : 200 -> 100 ---------------------------
    const float w20 = c2_w[0], w21 = c2_w[1], w22 = c2_w[2], w23 = c2_w[3], b2 = c2_b[0];
    float* y3 = buf;                         // c region dead
    #pragma unroll
    for (int it = 0; it < 4; ++it) {
        int i = lane + 32 * it;
        if (i < 100) {
            float v0 = (i == 0)          ? 0.0f : h2[2 * i - 1];
            float v1 = h2[2 * i];
            float v2 = h2[2 * i + 1];
            float v3 = (2 * i + 2 < 200) ? h2[2 * i + 2] : 0.0f;
            y3[i] = b2 + w20 * v0 + w21 * v1 + w22 * v2 + w23 * v3;
        }
    }
    __syncwarp();

    // --- Stage 3: maxpool2 + relu : 100 -> 50 -------------------------------
    float* h4 = buf + 256;
    #pragma unroll
    for (int it = 0; it < 2; ++it) {
        int i = lane + 32 * it;
        if (i < 50)
            h4[i] = fmaxf(fmaxf(y3[2 * i], y3[2 * i + 1]), 0.0f);
    }
    __syncwarp();

    // --- Stage 4: conv(k=4,s=2,p=1) : 50 -> 25 ------------------------------
    const float w40 = c4_w[0], w41 = c4_w[1], w42 = c4_w[2], w43 = c4_w[3], b4 = c4_b[0];
    float* y5 = buf;
    if (lane < 25) {
        int i = lane;
        float v0 = (i == 0)         ? 0.0f : h4[2 * i - 1];
        float v1 = h4[2 * i];
        float v2 = h4[2 * i + 1];
        float v3 = (2 * i + 2 < 50) ? h4[2 * i + 2] : 0.0f;
        y5[i] = b4 + w40 * v0 + w41 * v1 + w42 * v2 + w43 * v3;
    }
    __syncwarp();

    // --- Stage 5: maxpool2 + relu : 25 -> 12 --------------------------------
    float* h6 = buf + 128;
    if (lane < 12)
        h6[lane] = fmaxf(fmaxf(y5[2 * lane], y5[2 * lane + 1]), 0.0f);
    __syncwarp();

    // --- Stage 6: conv(k=4,s=2,p=1) : 12 -> 6 -------------------------------
    const float w60 = c6_w[0], w61 = c6_w[1], w62 = c6_w[2], w63 = c6_w[3], b6 = c6_b[0];
    float* y7 = buf;
    if (lane < 6) {
        int i = lane;
        float v0 = (i == 0)         ? 0.0f : h6[2 * i - 1];
        float v1 = h6[2 * i];
        float v2 = h6[2 * i + 1];
        float v3 = (2 * i + 2 < 12) ? h6[2 * i + 2] : 0.0f;
        y7[i] = b6 + w60 * v0 + w61 * v1 + w62 * v2 + w63 * v3;
    }
    __syncwarp();

    // --- Stage 7: maxpool2 + relu : 6 -> 3 ----------------------------------
    float* h8 = buf + 64;
    if (lane < 3)
        h8[lane] = fmaxf(fmaxf(y7[2 * lane], y7[2 * lane + 1]), 0.0f);
    __syncwarp();

    // --- Stage 8: conv(k=3,s=1,p=0) : 3 -> 1 --------------------------------
    if (lane == 0)
        g_feat[row] = c8_b[0] + c8_w[0] * h8[0] + c8_w[1] * h8[1] + c8_w[2] * h8[2];

    // ========================================================================
    // Per-batch last-block election (proven in R6: no atomic serialization).
    // ========================================================================
    const int b = blockIdx.x >> 7;               // batch id (128 blocks each)
    __syncthreads();                             // order all warps' g_feat STG
    if (threadIdx.x == 0) {
        __threadfence();                         // release this block's stores
        unsigned int prev = atomicAdd(&g_cnt[b * 64], 1u);
        s_last = (prev == (unsigned int)(BLOCKS_PER_BATCH - 1));
    }
    __syncthreads();
    if (!s_last) return;

    __threadfence();     // acquire: sibling blocks' g_feat stores visible

    // --- Classifier for batch b: logits[c] = feat[b,:].cls_w[c,:] + cls_b[c]
    {
        const float* __restrict__ f = g_feat + b * 1024;
        float a0 = 0.f, a1 = 0.f, a2 = 0.f;
        #pragma unroll
        for (int k = 0; k < 4; ++k) {
            int n = k * 256 + threadIdx.x;
            float v = __ldcg(f + n);
            a0 += v * __ldg(cls_w + n);
            a1 += v * __ldg(cls_w + 1024 + n);
            a2 += v * __ldg(cls_w + 2048 + n);
        }
        #pragma unroll
        for (int off = 16; off > 0; off >>= 1) {
            a0 += __shfl_down_sync(0xffffffffu, a0, off);
            a1 += __shfl_down_sync(0xffffffffu, a1, off);
            a2 += __shfl_down_sync(0xffffffffu, a2, off);
        }
        if (lane == 0) {
            s_red[0][warp] = a0;
            s_red[1][warp] = a1;
            s_red[2][warp] = a2;
        }
        __syncthreads();
        if (threadIdx.x == 0) {
            float l0 = cls_b[0], l1 = cls_b[1], l2 = cls_b[2];
            #pragma unroll
            for (int w = 0; w < WPB; ++w) {
                l0 += s_red[0][w];
                l1 += s_red[1][w];
                l2 += s_red[2][w];
            }
            float m  = fmaxf(l0, fmaxf(l1, l2));
            float e0 = expf(l0 - m), e1 = expf(l1 - m), e2 = expf(l2 - m);
            float inv = 1.0f / (e0 + e1 + e2);
            out[b * 3 + 0] = e0 * inv;
            out[b * 3 + 1] = e1 * inv;
            out[b * 3 + 2] = e2 * inv;
            g_cnt[b * 64] = 0;   // reset own counter for next graph replay
        }
    }
}

// ---------------------------------------------------------------------------
// Input order per metadata:
// 0:x 1:c0_w 2:c0_b 3:c2_w 4:c2_b 5:c4_w 6:c4_b 7:c6_w 8:c6_b 9:c8_w 10:c8_b
// 11..14: gcn weights (dead code, unused) 15:cls_w 16:cls_b
// ---------------------------------------------------------------------------
extern "C" void kernel_launch(void* const* d_in, const int* in_sizes, int n_in,
                              void* d_out, int out_size)
{
    const float* x     = (const float*)d_in[0];
    const float* c0_w  = (const float*)d_in[1];
    const float* c0_b  = (const float*)d_in[2];
    const float* c2_w  = (const float*)d_in[3];
    const float* c2_b  = (const float*)d_in[4];
    const float* c4_w  = (const float*)d_in[5];
    const float* c4_b  = (const float*)d_in[6];
    const float* c6_w  = (const float*)d_in[7];
    const float* c6_b  = (const float*)d_in[8];
    const float* c8_w  = (const float*)d_in[9];
    const float* c8_b  = (const float*)d_in[10];
    const float* cls_w = (const float*)d_in[15];
    const float* cls_b = (const float*)d_in[16];
    float* out = (float*)d_out;

    fused_kernel<<<NBLOCKS, WPB * 32>>>(
        x, c0_w, c0_b, c2_w, c2_b, c4_w, c4_b, c6_w, c6_b, c8_w, c8_b,
        cls_w, cls_b, out);
}

// round 12
// speedup vs baseline: 1.0979x; 1.0633x over previous
#include <cuda_runtime.h>

#define N_ROWS (64 * 1024)
#define T_LEN  1200
#define WPB    8                        // warps per block (proven config)
#define NBLOCKS (N_ROWS / WPB)          // 8192
#define BLOCKS_PER_BATCH 128            // 1024 nodes / 8 rows-per-block

// Scratch (allowed: __device__ globals, no allocation)
__device__ float        g_feat[N_ROWS];
// Per-batch completion counters, 256B apart (distinct LTS slices).
__device__ unsigned int g_cnt[64 * 64];

// ---------------------------------------------------------------------------
// Fused kernel (R6 body + stage-0 software pipelining): one warp per row.
// Stage 0+1 loads are prefetched one iteration ahead (MLP 3 -> 6) while
// keeping loads interleaved with compute (no front-batching -> no cross-CTA
// L1tex-queue spread). Ladder + per-batch sharded election proven in R6.
// Lengths: 1200 -> 600 -> 200 -> 100 -> 50 -> 25 -> 12 -> 6 -> 3 -> 1
// ---------------------------------------------------------------------------
__global__ __launch_bounds__(WPB * 32)
void fused_kernel(
    const float* __restrict__ x,
    const float* __restrict__ c0_w, const float* __restrict__ c0_b,
    const float* __restrict__ c2_w, const float* __restrict__ c2_b,
    const float* __restrict__ c4_w, const float* __restrict__ c4_b,
    const float* __restrict__ c6_w, const float* __restrict__ c6_b,
    const float* __restrict__ c8_w, const float* __restrict__ c8_b,
    const float* __restrict__ cls_w, const float* __restrict__ cls_b,
    float* __restrict__ out)
{
    __shared__ float sA[WPB][200];
    __shared__ float sB[WPB][100];
    __shared__ float s_red[3][WPB];
    __shared__ bool  s_last;

    const int warp = threadIdx.x >> 5;
    const int lane = threadIdx.x & 31;
    const int row  = blockIdx.x * WPB + warp;   // grid exactly covers N_ROWS

    const float2* __restrict__ xp =
        reinterpret_cast<const float2*>(x + (size_t)row * T_LEN);

    // --- Stage 0+1: conv(k=2,s=2) + maxpool3 + relu : 1200 -> 200 ----------
    // Lane j handles pool output j from x[6j..6j+5] (3 float2 loads).
    // One-iteration prefetch keeps ~6 loads in flight per warp.
    const float w00 = c0_w[0], w01 = c0_w[1], b0 = c0_b[0];
    float* h2 = sA[warp];
    {
        float2 A = xp[3 * lane];        // j0 = lane < 200 always valid
        float2 B = xp[3 * lane + 1];
        float2 C = xp[3 * lane + 2];
        #pragma unroll
        for (int it = 0; it < 7; ++it) {
            int j  = lane + 32 * it;
            int jn = j + 32;
            float2 A1 = A, B1 = B, C1 = C;
            if (jn < 200) {             // prefetch next iteration's loads
                A1 = xp[3 * jn];
                B1 = xp[3 * jn + 1];
                C1 = xp[3 * jn + 2];
            }
            if (j < 200) {
                float m0 = w00 * A.x + w01 * A.y;
                float m1 = w00 * B.x + w01 * B.y;
                float m2 = w00 * C.x + w01 * C.y;
                float m  = fmaxf(m0, fmaxf(m1, m2));
                h2[j] = fmaxf(m + b0, 0.0f);
            }
            A = A1; B = B1; C = C1;
        }
    }
    __syncwarp();

    // --- Stage 2: conv(k=4,s=2,p=1) : 200 -> 100 ---------------------------
    const float w20 = c2_w[0], w21 = c2_w[1], w22 = c2_w[2], w23 = c2_w[3], b2 = c2_b[0];
    float* y3 = sB[warp];
    #pragma unroll
    for (int it = 0; it < 4; ++it) {
        int i = lane + 32 * it;
        if (i < 100) {
            float v0 = (i == 0)          ? 0.0f : h2[2 * i - 1];
            float v1 = h2[2 * i];
            float v2 = h2[2 * i + 1];
            float v3 = (2 * i + 2 < 200) ? h2[2 * i + 2] : 0.0f;
            y3[i] = b2 + w20 * v0 + w21 * v1 + w22 * v2 + w23 * v3;
        }
    }
    __syncwarp();

    // --- Stage 3: maxpool2 + relu : 100 -> 50 -------------------------------
    float* h4 = sA[warp];
    #pragma unroll
    for (int it = 0; it < 2; ++it) {
        int i = lane + 32 * it;
        if (i < 50)
            h4[i] = fmaxf(fmaxf(y3[2 * i], y3[2 * i + 1]), 0.0f);
    }
    __syncwarp();

    // --- Stage 4: conv(k=4,s=2,p=1) : 50 -> 25 ------------------------------
    const float w40 = c4_w[0], w41 = c4_w[1], w42 = c4_w[2], w43 = c4_w[3], b4 = c4_b[0];
    float* y5 = sB[warp];
    if (lane < 25) {
        int i = lane;
        float v0 = (i == 0)         ? 0.0f : h4[2 * i - 1];
        float v1 = h4[2 * i];
        float v2 = h4[2 * i + 1];
        float v3 = (2 * i + 2 < 50) ? h4[2 * i + 2] : 0.0f;
        y5[i] = b4 + w40 * v0 + w41 * v1 + w42 * v2 + w43 * v3;
    }
    __syncwarp();

    // --- Stage 5: maxpool2 + relu : 25 -> 12 --------------------------------
    float* h6 = sA[warp];
    if (lane < 12)
        h6[lane] = fmaxf(fmaxf(y5[2 * lane], y5[2 * lane + 1]), 0.0f);
    __syncwarp();

    // --- Stage 6: conv(k=4,s=2,p=1) : 12 -> 6 -------------------------------
    const float w60 = c6_w[0], w61 = c6_w[1], w62 = c6_w[2], w63 = c6_w[3], b6 = c6_b[0];
    float* y7 = sB[warp];
    if (lane < 6) {
        int i = lane;
        float v0 = (i == 0)         ? 0.0f : h6[2 * i - 1];
        float v1 = h6[2 * i];
        float v2 = h6[2 * i + 1];
        float v3 = (2 * i + 2 < 12) ? h6[2 * i + 2] : 0.0f;
        y7[i] = b6 + w60 * v0 + w61 * v1 + w62 * v2 + w63 * v3;
    }
    __syncwarp();

    // --- Stage 7: maxpool2 + relu : 6 -> 3 ----------------------------------
    float* h8 = sA[warp];
    if (lane < 3)
        h8[lane] = fmaxf(fmaxf(y7[2 * lane], y7[2 * lane + 1]), 0.0f);
    __syncwarp();

    // --- Stage 8: conv(k=3,s=1,p=0) : 3 -> 1 --------------------------------
    if (lane == 0)
        g_feat[row] = c8_b[0] + c8_w[0] * h8[0] + c8_w[1] * h8[1] + c8_w[2] * h8[2];

    // ========================================================================
    // Per-batch last-block election (proven in R6: no atomic serialization).
    // ========================================================================
    const int b = blockIdx.x >> 7;               // batch id (128 blocks each)
    __syncthreads();                             // order all warps' g_feat STG
    if (threadIdx.x == 0) {
        __threadfence();                         // release this block's stores
        unsigned int prev = atomicAdd(&g_cnt[b * 64], 1u);
        s_last = (prev == (unsigned int)(BLOCKS_PER_BATCH - 1));
    }
    __syncthreads();
    if (!s_last) return;

    __threadfence();     // acquire: sibling blocks' g_feat stores visible

    // --- Classifier for batch b: logits[c] = feat[b,:].cls_w[c,:] + cls_b[c]
    {
        const float* __restrict__ f = g_feat + b * 1024;
        float a0 = 0.f, a1 = 0.f, a2 = 0.f;
        #pragma unroll
        for (int k = 0; k < 4; ++k) {
            int n = k * 256 + threadIdx.x;
            float v = __ldcg(f + n);
            a0 += v * __ldg(cls_w + n);
            a1 += v * __ldg(cls_w + 1024 + n);
            a2 += v * __ldg(cls_w + 2048 + n);
        }
        #pragma unroll
        for (int off = 16; off > 0; off >>= 1) {
            a0 += __shfl_down_sync(0xffffffffu, a0, off);
            a1 += __shfl_down_sync(0xffffffffu, a1, off);
            a2 += __shfl_down_sync(0xffffffffu, a2, off);
        }
        if (lane == 0) {
            s_red[0][warp] = a0;
            s_red[1][warp] = a1;
            s_red[2][warp] = a2;
        }
        __syncthreads();
        if (threadIdx.x == 0) {
            float l0 = cls_b[0], l1 = cls_b[1], l2 = cls_b[2];
            #pragma unroll
            for (int w = 0; w < WPB; ++w) {
                l0 += s_red[0][w];
                l1 += s_red[1][w];
                l2 += s_red[2][w];
            }
            float m  = fmaxf(l0, fmaxf(l1, l2));
            float e0 = expf(l0 - m), e1 = expf(l1 - m), e2 = expf(l2 - m);
            float inv = 1.0f / (e0 + e1 + e2);
            out[b * 3 + 0] = e0 * inv;
            out[b * 3 + 1] = e1 * inv;
            out[b * 3 + 2] = e2 * inv;
            g_cnt[b * 64] = 0;   // reset own counter for next graph replay
        }
    }
}

// ---------------------------------------------------------------------------
// Input order per metadata:
// 0:x 1:c0_w 2:c0_b 3:c2_w 4:c2_b 5:c4_w 6:c4_b 7:c6_w 8:c6_b 9:c8_w 10:c8_b
// 11..14: gcn weights (dead code, unused) 15:cls_w 16:cls_b
// ---------------------------------------------------------------------------
extern "C" void kernel_launch(void* const* d_in, const int* in_sizes, int n_in,
                              void* d_out, int out_size)
{
    const float* x     = (const float*)d_in[0];
    const float* c0_w  = (const float*)d_in[1];
    const float* c0_b  = (const float*)d_in[2];
    const float* c2_w  = (const float*)d_in[3];
    const float* c2_b  = (const float*)d_in[4];
    const float* c4_w  = (const float*)d_in[5];
    const float* c4_b  = (const float*)d_in[6];
    const float* c6_w  = (const float*)d_in[7];
    const float* c6_b  = (const float*)d_in[8];
    const float* c8_w  = (const float*)d_in[9];
    const float* c8_b  = (const float*)d_in[10];
    const float* cls_w = (const float*)d_in[15];
    const float* cls_b = (const float*)d_in[16];
    float* out = (float*)d_out;

    fused_kernel<<<NBLOCKS, WPB * 32>>>(
        x, c0_w, c0_b, c2_w, c2_b, c4_w, c4_b, c6_w, c6_b, c8_w, c8_b,
        cls_w, cls_b, out);
}

// round 15
// speedup vs baseline: 1.1181x; 1.0184x over previous
#include <cuda_runtime.h>

#define N_ROWS (64 * 1024)
#define T_LEN  1200
#define WPB    8                        // warps per block
#define ROWS_PER_WARP 2
#define NBLOCKS (N_ROWS / (WPB * ROWS_PER_WARP))   // 4096
#define BLOCKS_PER_BATCH 64             // 1024 nodes / 16 rows-per-block

// Scratch (allowed: __device__ globals, no allocation)
__device__ float        g_feat[N_ROWS];
// Per-batch completion counters, 256B apart (distinct LTS slices).
__device__ unsigned int g_cnt[64 * 64];

// ---------------------------------------------------------------------------
// Fused kernel: one warp per TWO rows. Stage 0+1 interleaves row-A and row-B
// loads (6 LDG.64 in flight, interleaved with compute). The conv/pool ladder
// then runs both rows together per step: two independent dependency chains
// double ILP in the otherwise load-free tail, amortizing it per byte loaded.
// Last block of each batch (64 blocks/batch) runs classifier + softmax.
// Lengths: 1200 -> 600 -> 200 -> 100 -> 50 -> 25 -> 12 -> 6 -> 3 -> 1
// ---------------------------------------------------------------------------
__global__ __launch_bounds__(WPB * 32)
void fused_kernel(
    const float* __restrict__ x,
    const float* __restrict__ c0_w, const float* __restrict__ c0_b,
    const float* __restrict__ c2_w, const float* __restrict__ c2_b,
    const float* __restrict__ c4_w, const float* __restrict__ c4_b,
    const float* __restrict__ c6_w, const float* __restrict__ c6_b,
    const float* __restrict__ c8_w, const float* __restrict__ c8_b,
    const float* __restrict__ cls_w, const float* __restrict__ cls_b,
    float* __restrict__ out)
{
    __shared__ float sA[WPB][2][200];
    __shared__ float sB[WPB][2][100];
    __shared__ float s_red[3][WPB];
    __shared__ bool  s_last;

    const int warp = threadIdx.x >> 5;
    const int lane = threadIdx.x & 31;
    const int row0 = (blockIdx.x * WPB + warp) * ROWS_PER_WARP;

    const float2* __restrict__ xpA =
        reinterpret_cast<const float2*>(x + (size_t)row0 * T_LEN);
    const float2* __restrict__ xpB =
        reinterpret_cast<const float2*>(x + (size_t)(row0 + 1) * T_LEN);

    // --- Stage 0+1: conv(k=2,s=2) + maxpool3 + relu : 1200 -> 200 (x2 rows)
    const float w00 = c0_w[0], w01 = c0_w[1], b0 = c0_b[0];
    float* h2A = sA[warp][0];
    float* h2B = sA[warp][1];
    #pragma unroll
    for (int it = 0; it < 7; ++it) {
        int j = lane + 32 * it;            // 7*32 = 224 >= 200
        if (j < 200) {
            float2 a0v = xpA[3 * j], b0v = xpA[3 * j + 1], c0v = xpA[3 * j + 2];
            float2 a1v = xpB[3 * j], b1v = xpB[3 * j + 1], c1v = xpB[3 * j + 2];
            float mA = fmaxf(w00 * a0v.x + w01 * a0v.y,
                       fmaxf(w00 * b0v.x + w01 * b0v.y,
                             w00 * c0v.x + w01 * c0v.y));
            float mB = fmaxf(w00 * a1v.x + w01 * a1v.y,
                       fmaxf(w00 * b1v.x + w01 * b1v.y,
                             w00 * c1v.x + w01 * c1v.y));
            h2A[j] = fmaxf(mA + b0, 0.0f);
            h2B[j] = fmaxf(mB + b0, 0.0f);
        }
    }
    __syncwarp();

    // --- Stage 2: conv(k=4,s=2,p=1) : 200 -> 100 (x2) ----------------------
    const float w20 = c2_w[0], w21 = c2_w[1], w22 = c2_w[2], w23 = c2_w[3], b2 = c2_b[0];
    float* y3A = sB[warp][0];
    float* y3B = sB[warp][1];
    #pragma unroll
    for (int it = 0; it < 4; ++it) {
        int i = lane + 32 * it;
        if (i < 100) {
            float aL = (i == 0)          ? 0.0f : h2A[2 * i - 1];
            float bL = (i == 0)          ? 0.0f : h2B[2 * i - 1];
            float aR = (2 * i + 2 < 200) ? h2A[2 * i + 2] : 0.0f;
            float bR = (2 * i + 2 < 200) ? h2B[2 * i + 2] : 0.0f;
            y3A[i] = b2 + w20 * aL + w21 * h2A[2*i] + w22 * h2A[2*i+1] + w23 * aR;
            y3B[i] = b2 + w20 * bL + w21 * h2B[2*i] + w22 * h2B[2*i+1] + w23 * bR;
        }
    }
    __syncwarp();

    // --- Stage 3: maxpool2 + relu : 100 -> 50 (x2) --------------------------
    float* h4A = sA[warp][0];
    float* h4B = sA[warp][1];
    #pragma unroll
    for (int it = 0; it < 2; ++it) {
        int i = lane + 32 * it;
        if (i < 50) {
            h4A[i] = fmaxf(fmaxf(y3A[2 * i], y3A[2 * i + 1]), 0.0f);
            h4B[i] = fmaxf(fmaxf(y3B[2 * i], y3B[2 * i + 1]), 0.0f);
        }
    }
    __syncwarp();

    // --- Stage 4: conv(k=4,s=2,p=1) : 50 -> 25 (x2) -------------------------
    const float w40 = c4_w[0], w41 = c4_w[1], w42 = c4_w[2], w43 = c4_w[3], b4 = c4_b[0];
    float* y5A = sB[warp][0];
    float* y5B = sB[warp][1];
    if (lane < 25) {
        int i = lane;
        float aL = (i == 0)         ? 0.0f : h4A[2 * i - 1];
        float bL = (i == 0)         ? 0.0f : h4B[2 * i - 1];
        float aR = (2 * i + 2 < 50) ? h4A[2 * i + 2] : 0.0f;
        float bR = (2 * i + 2 < 50) ? h4B[2 * i + 2] : 0.0f;
        y5A[i] = b4 + w40 * aL + w41 * h4A[2*i] + w42 * h4A[2*i+1] + w43 * aR;
        y5B[i] = b4 + w40 * bL + w41 * h4B[2*i] + w42 * h4B[2*i+1] + w43 * bR;
    }
    __syncwarp();

    // --- Stage 5: maxpool2 + relu : 25 -> 12 (x2) ---------------------------
    float* h6A = sA[warp][0];
    float* h6B = sA[warp][1];
    if (lane < 12) {
        h6A[lane] = fmaxf(fmaxf(y5A[2 * lane], y5A[2 * lane + 1]), 0.0f);
        h6B[lane] = fmaxf(fmaxf(y5B[2 * lane], y5B[2 * lane + 1]), 0.0f);
    }
    __syncwarp();

    // --- Stage 6: conv(k=4,s=2,p=1) : 12 -> 6 (x2) --------------------------
    const float w60 = c6_w[0], w61 = c6_w[1], w62 = c6_w[2], w63 = c6_w[3], b6 = c6_b[0];
    float* y7A = sB[warp][0];
    float* y7B = sB[warp][1];
    if (lane < 6) {
        int i = lane;
        float aL = (i == 0)         ? 0.0f : h6A[2 * i - 1];
        float bL = (i == 0)         ? 0.0f : h6B[2 * i - 1];
        float aR = (2 * i + 2 < 12) ? h6A[2 * i + 2] : 0.0f;
        float bR = (2 * i + 2 < 12) ? h6B[2 * i + 2] : 0.0f;
        y7A[i] = b6 + w60 * aL + w61 * h6A[2*i] + w62 * h6A[2*i+1] + w63 * aR;
        y7B[i] = b6 + w60 * bL + w61 * h6B[2*i] + w62 * h6B[2*i+1] + w63 * bR;
    }
    __syncwarp();

    // --- Stage 7: maxpool2 + relu : 6 -> 3 (x2) -----------------------------
    float* h8A = sA[warp][0];
    float* h8B = sA[warp][1];
    if (lane < 3) {
        h8A[lane] = fmaxf(fmaxf(y7A[2 * lane], y7A[2 * lane + 1]), 0.0f);
        h8B[lane] = fmaxf(fmaxf(y7B[2 * lane], y7B[2 * lane + 1]), 0.0f);
    }
    __syncwarp();

    // --- Stage 8: conv(k=3,s=1,p=0) : 3 -> 1 (x2) ---------------------------
    if (lane == 0) {
        g_feat[row0]     = c8_b[0] + c8_w[0]*h8A[0] + c8_w[1]*h8A[1] + c8_w[2]*h8A[2];
        g_feat[row0 + 1] = c8_b[0] + c8_w[0]*h8B[0] + c8_w[1]*h8B[1] + c8_w[2]*h8B[2];
    }

    // ========================================================================
    // Per-batch last-block election (sharded counters; proven in R6).
    // ========================================================================
    const int b = blockIdx.x >> 6;               // batch id (64 blocks each)
    __syncthreads();                             // order all warps' g_feat STG
    if (threadIdx.x == 0) {
        __threadfence();                         // release this block's stores
        unsigned int prev = atomicAdd(&g_cnt[b * 64], 1u);
        s_last = (prev == (unsigned int)(BLOCKS_PER_BATCH - 1));
    }
    __syncthreads();
    if (!s_last) return;

    __threadfence();     // acquire: sibling blocks' g_feat stores visible

    // --- Classifier for batch b: logits[c] = feat[b,:].cls_w[c,:] + cls_b[c]
    {
        const float* __restrict__ f = g_feat + b * 1024;
        float a0 = 0.f, a1 = 0.f, a2 = 0.f;
        #pragma unroll
        for (int k = 0; k < 4; ++k) {
            int n = k * 256 + threadIdx.x;
            float v = __ldcg(f + n);
            a0 += v * __ldg(cls_w + n);
            a1 += v * __ldg(cls_w + 1024 + n);
            a2 += v * __ldg(cls_w + 2048 + n);
        }
        #pragma unroll
        for (int off = 16; off > 0; off >>= 1) {
            a0 += __shfl_down_sync(0xffffffffu, a0, off);
            a1 += __shfl_down_sync(0xffffffffu, a1, off);
            a2 += __shfl_down_sync(0xffffffffu, a2, off);
        }
        if (lane == 0) {
            s_red[0][warp] = a0;
            s_red[1][warp] = a1;
            s_red[2][warp] = a2;
        }
        __syncthreads();
        if (threadIdx.x == 0) {
            float l0 = cls_b[0], l1 = cls_b[1], l2 = cls_b[2];
            #pragma unroll
            for (int w = 0; w < WPB; ++w) {
                l0 += s_red[0][w];
                l1 += s_red[1][w];
                l2 += s_red[2][w];
            }
            float m  = fmaxf(l0, fmaxf(l1, l2));
            float e0 = expf(l0 - m), e1 = expf(l1 - m), e2 = expf(l2 - m);
            float inv = 1.0f / (e0 + e1 + e2);
            out[b * 3 + 0] = e0 * inv;
            out[b * 3 + 1] = e1 * inv;
            out[b * 3 + 2] = e2 * inv;
            g_cnt[b * 64] = 0;   // reset own counter for next graph replay
        }
    }
}

// ---------------------------------------------------------------------------
// Input order per metadata:
// 0:x 1:c0_w 2:c0_b 3:c2_w 4:c2_b 5:c4_w 6:c4_b 7:c6_w 8:c6_b 9:c8_w 10:c8_b
// 11..14: gcn weights (dead code, unused) 15:cls_w 16:cls_b
// ---------------------------------------------------------------------------
extern "C" void kernel_launch(void* const* d_in, const int* in_sizes, int n_in,
                              void* d_out, int out_size)
{
    const float* x     = (const float*)d_in[0];
    const float* c0_w  = (const float*)d_in[1];
    const float* c0_b  = (const float*)d_in[2];
    const float* c2_w  = (const float*)d_in[3];
    const float* c2_b  = (const float*)d_in[4];
    const float* c4_w  = (const float*)d_in[5];
    const float* c4_b  = (const float*)d_in[6];
    const float* c6_w  = (const float*)d_in[7];
    const float* c6_b  = (const float*)d_in[8];
    const float* c8_w  = (const float*)d_in[9];
    const float* c8_b  = (const float*)d_in[10];
    const float* cls_w = (const float*)d_in[15];
    const float* cls_b = (const float*)d_in[16];
    float* out = (float*)d_out;

    fused_kernel<<<NBLOCKS, WPB * 32>>>(
        x, c0_w, c0_b, c2_w, c2_b, c4_w, c4_b, c6_w, c6_b, c8_w, c8_b,
        cls_w, cls_b, out);
}

// round 17
// speedup vs baseline: 1.1410x; 1.0205x over previous
#include <cuda_runtime.h>

#define N_ROWS (64 * 1024)
#define T_LEN  1200
#define WPB    8                        // warps per block
#define ROWS_PER_WARP 2
#define NBLOCKS (N_ROWS / (WPB * ROWS_PER_WARP))   // 4096
#define BLOCKS_PER_BATCH 64             // 1024 nodes / 16 rows-per-block

// Scratch (allowed: __device__ globals, no allocation)
__device__ float        g_feat[N_ROWS];
// Per-batch completion counters, 256B apart (distinct LTS slices).
__device__ unsigned int g_cnt[64 * 64];

// ---------------------------------------------------------------------------
// Fused kernel: one warp per TWO rows. Stage 0+1 (conv k2s2 + pool3 + relu)
// is computed from lane-private float4 loads: lane handles pool-output PAIR p
// per row -> 3 LDG.128 -> 6 convs -> 2 pool outputs (one float2 STS).
// 4 iterations instead of 7; ~25% fewer instructions than the LDG.64 form.
// Ladder processes both rows per step (2 independent chains = tail ILP).
// Last block of each batch (64 blocks/batch) runs classifier + softmax.
// Lengths: 1200 -> 600 -> 200 -> 100 -> 50 -> 25 -> 12 -> 6 -> 3 -> 1
// ---------------------------------------------------------------------------
__global__ __launch_bounds__(WPB * 32)
void fused_kernel(
    const float* __restrict__ x,
    const float* __restrict__ c0_w, const float* __restrict__ c0_b,
    const float* __restrict__ c2_w, const float* __restrict__ c2_b,
    const float* __restrict__ c4_w, const float* __restrict__ c4_b,
    const float* __restrict__ c6_w, const float* __restrict__ c6_b,
    const float* __restrict__ c8_w, const float* __restrict__ c8_b,
    const float* __restrict__ cls_w, const float* __restrict__ cls_b,
    float* __restrict__ out)
{
    __shared__ float sA[WPB][2][200];
    __shared__ float sB[WPB][2][100];
    __shared__ float s_red[3][WPB];
    __shared__ bool  s_last;

    const int warp = threadIdx.x >> 5;
    const int lane = threadIdx.x & 31;
    const int row0 = (blockIdx.x * WPB + warp) * ROWS_PER_WARP;

    // Rows are 16B-aligned: 1200 floats * 4B = 4800B = 300 * 16B.
    const float4* __restrict__ xpA =
        reinterpret_cast<const float4*>(x + (size_t)row0 * T_LEN);
    const float4* __restrict__ xpB =
        reinterpret_cast<const float4*>(x + (size_t)(row0 + 1) * T_LEN);

    // --- Stage 0+1: conv(k=2,s=2) + maxpool3 + relu : 1200 -> 200 (x2 rows)
    // Pool pair p (p<100): x4[3p..3p+2] -> pool outputs {2p, 2p+1}.
    const float w0 = c0_w[0], w1 = c0_w[1], b0 = c0_b[0];
    float2* h2Av = reinterpret_cast<float2*>(sA[warp][0]);
    float2* h2Bv = reinterpret_cast<float2*>(sA[warp][1]);
    #pragma unroll
    for (int it = 0; it < 4; ++it) {
        int p = lane + 32 * it;            // 4*32 = 128 >= 100
        if (p < 100) {
            float4 A0 = xpA[3 * p], B0 = xpA[3 * p + 1], C0 = xpA[3 * p + 2];
            float4 A1 = xpB[3 * p], B1 = xpB[3 * p + 1], C1 = xpB[3 * p + 2];
            float eA = fmaxf(w0 * A0.x + w1 * A0.y,
                       fmaxf(w0 * A0.z + w1 * A0.w, w0 * B0.x + w1 * B0.y));
            float oA = fmaxf(w0 * B0.z + w1 * B0.w,
                       fmaxf(w0 * C0.x + w1 * C0.y, w0 * C0.z + w1 * C0.w));
            float eB = fmaxf(w0 * A1.x + w1 * A1.y,
                       fmaxf(w0 * A1.z + w1 * A1.w, w0 * B1.x + w1 * B1.y));
            float oB = fmaxf(w0 * B1.z + w1 * B1.w,
                       fmaxf(w0 * C1.x + w1 * C1.y, w0 * C1.z + w1 * C1.w));
            h2Av[p] = make_float2(fmaxf(eA + b0, 0.0f), fmaxf(oA + b0, 0.0f));
            h2Bv[p] = make_float2(fmaxf(eB + b0, 0.0f), fmaxf(oB + b0, 0.0f));
        }
    }
    __syncwarp();

    float* h2A = sA[warp][0];
    float* h2B = sA[warp][1];

    // --- Stage 2: conv(k=4,s=2,p=1) : 200 -> 100 (x2) ----------------------
    const float w20 = c2_w[0], w21 = c2_w[1], w22 = c2_w[2], w23 = c2_w[3], b2 = c2_b[0];
    float* y3A = sB[warp][0];
    float* y3B = sB[warp][1];
    #pragma unroll
    for (int it = 0; it < 4; ++it) {
        int i = lane + 32 * it;
        if (i < 100) {
            float aL = (i == 0)          ? 0.0f : h2A[2 * i - 1];
            float bL = (i == 0)          ? 0.0f : h2B[2 * i - 1];
            float aR = (2 * i + 2 < 200) ? h2A[2 * i + 2] : 0.0f;
            float bR = (2 * i + 2 < 200) ? h2B[2 * i + 2] : 0.0f;
            y3A[i] = b2 + w20 * aL + w21 * h2A[2*i] + w22 * h2A[2*i+1] + w23 * aR;
            y3B[i] = b2 + w20 * bL + w21 * h2B[2*i] + w22 * h2B[2*i+1] + w23 * bR;
        }
    }
    __syncwarp();

    // --- Stage 3: maxpool2 + relu : 100 -> 50 (x2) --------------------------
    float* h4A = sA[warp][0];
    float* h4B = sA[warp][1];
    #pragma unroll
    for (int it = 0; it < 2; ++it) {
        int i = lane + 32 * it;
        if (i < 50) {
            h4A[i] = fmaxf(fmaxf(y3A[2 * i], y3A[2 * i + 1]), 0.0f);
            h4B[i] = fmaxf(fmaxf(y3B[2 * i], y3B[2 * i + 1]), 0.0f);
        }
    }
    __syncwarp();

    // --- Stage 4: conv(k=4,s=2,p=1) : 50 -> 25 (x2) -------------------------
    const float w40 = c4_w[0], w41 = c4_w[1], w42 = c4_w[2], w43 = c4_w[3], b4 = c4_b[0];
    float* y5A = sB[warp][0];
    float* y5B = sB[warp][1];
    if (lane < 25) {
        int i = lane;
        float aL = (i == 0)         ? 0.0f : h4A[2 * i - 1];
        float bL = (i == 0)         ? 0.0f : h4B[2 * i - 1];
        float aR = (2 * i + 2 < 50) ? h4A[2 * i + 2] : 0.0f;
        float bR = (2 * i + 2 < 50) ? h4B[2 * i + 2] : 0.0f;
        y5A[i] = b4 + w40 * aL + w41 * h4A[2*i] + w42 * h4A[2*i+1] + w43 * aR;
        y5B[i] = b4 + w40 * bL + w41 * h4B[2*i] + w42 * h4B[2*i+1] + w43 * bR;
    }
    __syncwarp();

    // --- Stage 5: maxpool2 + relu : 25 -> 12 (x2) ---------------------------
    float* h6A = sA[warp][0];
    float* h6B = sA[warp][1];
    if (lane < 12) {
        h6A[lane] = fmaxf(fmaxf(y5A[2 * lane], y5A[2 * lane + 1]), 0.0f);
        h6B[lane] = fmaxf(fmaxf(y5B[2 * lane], y5B[2 * lane + 1]), 0.0f);
    }
    __syncwarp();

    // --- Stage 6: conv(k=4,s=2,p=1) : 12 -> 6 (x2) --------------------------
    const float w60 = c6_w[0], w61 = c6_w[1], w62 = c6_w[2], w63 = c6_w[3], b6 = c6_b[0];
    float* y7A = sB[warp][0];
    float* y7B = sB[warp][1];
    if (lane < 6) {
        int i = lane;
        float aL = (i == 0)         ? 0.0f : h6A[2 * i - 1];
        float bL = (i == 0)         ? 0.0f : h6B[2 * i - 1];
        float aR = (2 * i + 2 < 12) ? h6A[2 * i + 2] : 0.0f;
        float bR = (2 * i + 2 < 12) ? h6B[2 * i + 2] : 0.0f;
        y7A[i] = b6 + w60 * aL + w61 * h6A[2*i] + w62 * h6A[2*i+1] + w63 * aR;
        y7B[i] = b6 + w60 * bL + w61 * h6B[2*i] + w62 * h6B[2*i+1] + w63 * bR;
    }
    __syncwarp();

    // --- Stage 7: maxpool2 + relu : 6 -> 3 (x2) -----------------------------
    float* h8A = sA[warp][0];
    float* h8B = sA[warp][1];
    if (lane < 3) {
        h8A[lane] = fmaxf(fmaxf(y7A[2 * lane], y7A[2 * lane + 1]), 0.0f);
        h8B[lane] = fmaxf(fmaxf(y7B[2 * lane], y7B[2 * lane + 1]), 0.0f);
    }
    __syncwarp();

    // --- Stage 8: conv(k=3,s=1,p=0) : 3 -> 1 (x2) ---------------------------
    if (lane == 0) {
        g_feat[row0]     = c8_b[0] + c8_w[0]*h8A[0] + c8_w[1]*h8A[1] + c8_w[2]*h8A[2];
        g_feat[row0 + 1] = c8_b[0] + c8_w[0]*h8B[0] + c8_w[1]*h8B[1] + c8_w[2]*h8B[2];
    }

    // ========================================================================
    // Per-batch last-block election (sharded counters; proven in R6).
    // ========================================================================
    const int b = blockIdx.x >> 6;               // batch id (64 blocks each)
    __syncthreads();                             // order all warps' g_feat STG
    if (threadIdx.x == 0) {
        __threadfence();                         // release this block's stores
        unsigned int prev = atomicAdd(&g_cnt[b * 64], 1u);
        s_last = (prev == (unsigned int)(BLOCKS_PER_BATCH - 1));
    }
    __syncthreads();
    if (!s_last) return;

    __threadfence();     // acquire: sibling blocks' g_feat stores visible

    // --- Classifier for batch b: logits[c] = feat[b,:].cls_w[c,:] + cls_b[c]
    {
        const float* __restrict__ f = g_feat + b * 1024;
        float a0 = 0.f, a1 = 0.f, a2 = 0.f;
        #pragma unroll
        for (int k = 0; k < 4; ++k) {
            int n = k * 256 + threadIdx.x;
            float v = __ldcg(f + n);
            a0 += v * __ldg(cls_w + n);
            a1 += v * __ldg(cls_w + 1024 + n);
            a2 += v * __ldg(cls_w + 2048 + n);
        }
        #pragma unroll
        for (int off = 16; off > 0; off >>= 1) {
            a0 += __shfl_down_sync(0xffffffffu, a0, off);
            a1 += __shfl_down_sync(0xffffffffu, a1, off);
            a2 += __shfl_down_sync(0xffffffffu, a2, off);
        }
        if (lane == 0) {
            s_red[0][warp] = a0;
            s_red[1][warp] = a1;
            s_red[2][warp] = a2;
        }
        __syncthreads();
        if (threadIdx.x == 0) {
            float l0 = cls_b[0], l1 = cls_b[1], l2 = cls_b[2];
            #pragma unroll
            for (int w = 0; w < WPB; ++w) {
                l0 += s_red[0][w];
                l1 += s_red[1][w];
                l2 += s_red[2][w];
            }
            float m  = fmaxf(l0, fmaxf(l1, l2));
            float e0 = expf(l0 - m), e1 = expf(l1 - m), e2 = expf(l2 - m);
            float inv = 1.0f / (e0 + e1 + e2);
            out[b * 3 + 0] = e0 * inv;
            out[b * 3 + 1] = e1 * inv;
            out[b * 3 + 2] = e2 * inv;
            g_cnt[b * 64] = 0;   // reset own counter for next graph replay
        }
    }
}

// ---------------------------------------------------------------------------
// Input order per metadata:
// 0:x 1:c0_w 2:c0_b 3:c2_w 4:c2_b 5:c4_w 6:c4_b 7:c6_w 8:c6_b 9:c8_w 10:c8_b
// 11..14: gcn weights (dead code, unused) 15:cls_w 16:cls_b
// ---------------------------------------------------------------------------
extern "C" void kernel_launch(void* const* d_in, const int* in_sizes, int n_in,
                              void* d_out, int out_size)
{
    const float* x     = (const float*)d_in[0];
    const float* c0_w  = (const float*)d_in[1];
    const float* c0_b  = (const float*)d_in[2];
    const float* c2_w  = (const float*)d_in[3];
    const float* c2_b  = (const float*)d_in[4];
    const float* c4_w  = (const float*)d_in[5];
    const float* c4_b  = (const float*)d_in[6];
    const float* c6_w  = (const float*)d_in[7];
    const float* c6_b  = (const float*)d_in[8];
    const float* c8_w  = (const float*)d_in[9];
    const float* c8_b  = (const float*)d_in[10];
    const float* cls_w = (const float*)d_in[15];
    const float* cls_b = (const float*)d_in[16];
    float* out = (float*)d_out;

    fused_kernel<<<NBLOCKS, WPB * 32>>>(
        x, c0_w, c0_b, c2_w, c2_b, c4_w, c4_b, c6_w, c6_b, c8_w, c8_b,
        cls_w, cls_b, out);
}